// round 14
// baseline (speedup 1.0000x reference)
#include <cuda_runtime.h>
#include <cstddef>
#include <cstdint>

#define BATCH 8192
#define NSEQ 50
#define NUM_NODES 200000
#define TD 16
#define DH 64
#define G3 192
#define RW 6           // batch rows per fused block
#define TC 10          // timesteps per chunk
#define NCH (NSEQ / TC)
#define THR 384
#define NB 32          // nodes per k_nodeQ block

typedef unsigned long long u64;

// ---------------- static device scratch ----------------
__device__ float g_P[(size_t)NUM_NODES * DH];      // node_raw @ W_feat
__device__ float g_Q[(size_t)NUM_NODES * G3];      // node_raw @ (W_feat @ sWih^T)
__device__ float g_skill[NUM_NODES];
__device__ u64   g_Gp[32 * 256];                   // packed combined [Q|P] weight table
__device__ u64   g_M2[2 * 8 * G3];                 // packed M = W_ih @ W_time^T per side
__device__ float g_v[2 * 3 * G3];                  // v0 (const+bias), v1 (struct), v2 (edge)

// ---------------- packed f32x2 helpers ----------------
__device__ __forceinline__ u64 pack2(float lo, float hi) {
    u64 d; asm("mov.b64 %0, {%1, %2};" : "=l"(d) : "f"(lo), "f"(hi)); return d;
}
__device__ __forceinline__ void unpack2(u64 v, float& lo, float& hi) {
    asm("mov.b64 {%0, %1}, %2;" : "=f"(lo), "=f"(hi) : "l"(v));
}
__device__ __forceinline__ u64 ffma2(u64 a, u64 b, u64 c) {
    u64 d; asm("fma.rn.f32x2 %0, %1, %2, %3;" : "=l"(d) : "l"(a), "l"(b), "l"(c));
    return d;
}
__device__ __forceinline__ void lds_v2u64(uint32_t addr, u64& a, u64& b) {
    asm volatile("ld.shared.v2.b64 {%0, %1}, [%2];" : "=l"(a), "=l"(b) : "r"(addr));
}
__device__ __forceinline__ u64 lds_u64(uint32_t addr) {
    u64 a; asm volatile("ld.shared.b64 %0, [%1];" : "=l"(a) : "r"(addr)); return a;
}
__device__ __forceinline__ uint32_t smem_u32(const void* p) {
    return (uint32_t)__cvta_generic_to_shared(p);
}

// ---------------- math helpers ----------------
__device__ __forceinline__ float cos_acc(float x) {
    const double TP = 6.283185307179586476925287;
    const float C1 = 6.28125f;
    const float C2 = (float)(TP - (double)C1);
    const float C3 = (float)(TP - (double)C1 - (double)((float)(TP - (double)C1)));
    const float INV2PI = 0.15915494309189535f;
    float k = rintf(x * INV2PI);
    float r = fmaf(-k, C1, x);
    r = fmaf(-k, C2, r);
    r = fmaf(-k, C3, r);
    return __cosf(r);
}
__device__ __forceinline__ float sigmoid_(float x) {
    float e = __expf(-x);
    return __fdividef(1.0f, 1.0f + e);
}
__device__ __forceinline__ float tanh_(float x) {
    float e = __expf(-2.0f * x);
    return __fdividef(2.0f, 1.0f + e) - 1.0f;
}

// ---------------- K1: derived weight tables ----------------
__global__ void __launch_bounds__(384) k_ww(
    const float* __restrict__ Wf, const float* __restrict__ sWih,
    const float* __restrict__ dWih, const float* __restrict__ sbih,
    const float* __restrict__ dbih, const float* __restrict__ Wt,
    const float* __restrict__ Wstr, const float* __restrict__ Wedg,
    const float* __restrict__ bf, const float* __restrict__ be,
    const float* __restrict__ bt, const float* __restrict__ bs)
{
    __shared__ float sm[4096];
    const int tid = threadIdx.x;
    if (blockIdx.x == 0) {
        for (int i = tid; i < 4096; i += 384) sm[i] = Wf[i];
        __syncthreads();
        if (tid < 256) {
            const int c = tid;
            if (c < 192) {
                float row[64];
                const float4* rp = (const float4*)(sWih + (size_t)c * 64);
#pragma unroll
                for (int q4 = 0; q4 < 16; q4++) {
                    float4 v = rp[q4];
                    row[4*q4] = v.x; row[4*q4+1] = v.y; row[4*q4+2] = v.z; row[4*q4+3] = v.w;
                }
#pragma unroll
                for (int q = 0; q < 32; q++) {
                    float a0 = 0.f, a1 = 0.f;
#pragma unroll
                    for (int j = 0; j < 64; j++) {
                        a0 = fmaf(row[j], sm[(2*q)*64 + j], a0);
                        a1 = fmaf(row[j], sm[(2*q+1)*64 + j], a1);
                    }
                    g_Gp[q * 256 + c] = pack2(a0, a1);
                }
            } else {
                const int m2 = c - 192;
#pragma unroll
                for (int q = 0; q < 32; q++)
                    g_Gp[q * 256 + c] = pack2(sm[(2*q)*64 + m2], sm[(2*q+1)*64 + m2]);
            }
        }
    } else {
        for (int i = tid; i < 1024; i += 384) sm[i] = Wt[i];
        if (tid < 64) {
            sm[1024 + tid] = Wstr[tid];
            sm[1088 + tid] = Wedg[tid];
            sm[1152 + tid] = be[tid] + bt[tid] + 2.f * bs[tid] + bf[tid];  // src C
            sm[1216 + tid] = be[tid] + bt[tid] + bs[tid];                  // dst C
        }
        __syncthreads();
        const int side = tid / G3, k = tid % G3;
        const float* Wih = side ? dWih : sWih;
        const float* bihp = side ? dbih : sbih;
        float row[64];
        const float4* rp = (const float4*)(Wih + (size_t)k * 64);
#pragma unroll
        for (int q4 = 0; q4 < 16; q4++) {
            float4 v = rp[q4];
            row[4*q4] = v.x; row[4*q4+1] = v.y; row[4*q4+2] = v.z; row[4*q4+3] = v.w;
        }
        float M[16];
#pragma unroll
        for (int kk = 0; kk < 16; kk++) {
            float a = 0.f;
#pragma unroll
            for (int j = 0; j < 64; j++) a = fmaf(row[j], sm[kk * 64 + j], a);
            M[kk] = a;
        }
        float v1 = 0.f, v2 = 0.f, v0 = bihp[k];
#pragma unroll
        for (int j = 0; j < 64; j++) {
            v1 = fmaf(row[j], sm[1024 + j], v1);
            v2 = fmaf(row[j], sm[1088 + j], v2);
            v0 = fmaf(row[j], sm[1152 + side * 64 + j], v0);
        }
#pragma unroll
        for (int q = 0; q < 8; q++)
            g_M2[(side * 8 + q) * G3 + k] = pack2(M[2*q], M[2*q+1]);
        g_v[(side * 3 + 0) * G3 + k] = v0;
        g_v[(side * 3 + 1) * G3 + k] = v1;
        g_v[(side * 3 + 2) * G3 + k] = v2;
    }
}

// ---------------- K2: per-node Q (192) + P (64) + skill tables ----------------
__global__ void __launch_bounds__(256) k_nodeQ(const float* __restrict__ nodef) {
    __shared__ __align__(16) float rows[NB][64];
    const int tid = threadIdx.x;
    const int n0 = blockIdx.x * NB;
    for (int i = tid; i < NB * 64; i += 256) ((float*)rows)[i] = nodef[(size_t)n0 * 64 + i];
    __syncthreads();
    u64 w[32];
#pragma unroll
    for (int q = 0; q < 32; q++) w[q] = g_Gp[q * 256 + tid];
    const uint32_t rb = smem_u32(rows);
#pragma unroll 2
    for (int nn = 0; nn < NB; nn++) {
        const uint32_t ra = rb + nn * 256;
        u64 a0 = 0ull, a1 = 0ull;
#pragma unroll
        for (int q = 0; q < 16; q++) {
            u64 p, qq;
            lds_v2u64(ra + q * 16, p, qq);
            a0 = ffma2(w[2*q], p, a0);
            a1 = ffma2(w[2*q+1], qq, a1);
        }
        float lo, hi, lo2, hi2;
        unpack2(a0, lo, hi); unpack2(a1, lo2, hi2);
        const float val = (lo + hi) + (lo2 + hi2);
        const int n = n0 + nn;
        if (tid < 192) g_Q[(size_t)n * G3 + tid] = val;
        else g_P[(size_t)n * 64 + (tid - 192)] = val;
    }
    if (tid < NB) g_skill[n0 + tid] = rows[tid][0];
}

// ---------------- fused gi + GRU kernel (quarter-split, output-pair gh) ----------------
struct SMF {
    float gi[TC][RW][G3];              // 46080
    float ghQ[RW][4][G3];              // 18432 : gh quarter-partials
    u64   M2s[8][G3];                  // 12288
    __align__(16) float te[TC][RW][TD];//  3840
    __align__(16) float h[RW][DH];     //  1536
    float sf[RW][NSEQ];                //  1200
    float e0[RW][NSEQ];                //  1200
    float dt[RW][NSEQ];                //  1200
    int   nid[RW][NSEQ];               //  1200
    float tailv[DH];                   //   256
    float tw[TD], tb[TD];              //   128
};

template <bool HAS_NODE>
__global__ void __launch_bounds__(THR, 2) k_fused(
    const int* __restrict__ nbr_nid, const int* __restrict__ nbr_eid,
    const float* __restrict__ nbr_ts, const float* __restrict__ t_int,
    const int* __restrict__ other_ids, const int* __restrict__ epi_ids,
    const float* __restrict__ edge_raw, const float* __restrict__ W_time,
    const float* __restrict__ time_w, const float* __restrict__ time_b,
    const float* __restrict__ W_edge, const float* __restrict__ b_feat,
    const float* __restrict__ b_edge, const float* __restrict__ b_time,
    const float* __restrict__ W_hh, const float* __restrict__ b_hh,
    const u64* __restrict__ M2g, const float* __restrict__ vg,
    const float* __restrict__ W_out, const float* __restrict__ b_out,
    float* __restrict__ outp)
{
    extern __shared__ char smraw[];
    SMF* s = (SMF*)smraw;
    const int tid = threadIdx.x;
    const int b0 = blockIdx.x * RW;
    const int rows = min(RW, BATCH - b0);
    // gi role: full 16-dots, slot group
    const int kg = tid % G3, sg = tid / G3;
    // gh role: output pair x quarter
    const int kp = tid % 96, qq = tid / 96;      // kp: outputs 2kp,2kp+1 ; qq: 0..3
    const int k0 = 2 * kp;
    // gates role
    const int rg = tid >> 6, j = tid & 63;

    // persistent regs: W_hh quarter-rows for 2 outputs + packed bias init
    u64 wA[8], wB[8];
    {
        const float4* wpA = (const float4*)(W_hh + (size_t)k0 * 64 + qq * 16);
        const float4* wpB = (const float4*)(W_hh + (size_t)(k0 + 1) * 64 + qq * 16);
#pragma unroll
        for (int q = 0; q < 4; q++) {
            float4 a = wpA[q], b = wpB[q];
            wA[2*q] = pack2(a.x, a.y); wA[2*q+1] = pack2(a.z, a.w);
            wB[2*q] = pack2(b.x, b.y); wB[2*q+1] = pack2(b.z, b.w);
        }
    }
    const u64 biA = qq ? 0ull : pack2(b_hh[k0], 0.f);
    const u64 biB = qq ? 0ull : pack2(b_hh[k0 + 1], 0.f);
    const float v0k = vg[kg], v1k = vg[G3 + kg], v2k = vg[2 * G3 + kg];

    // ---- init ----
    for (int i = tid; i < 8 * G3; i += THR) ((u64*)s->M2s)[i] = M2g[i];
    if (tid < 64) {
        float tl = b_time[tid] + b_edge[tid] + edge_raw[0] * W_edge[tid];
        if (!HAS_NODE) tl += b_feat[tid];
#pragma unroll
        for (int kk = 0; kk < TD; kk++)
            tl = fmaf(cos_acc(time_b[kk]), W_time[kk * 64 + tid], tl);
        s->tailv[tid] = tl;
    } else if (tid < 80) {
        s->tw[tid - 64] = time_w[tid - 64];
        s->tb[tid - 64] = time_b[tid - 64];
    }
    for (int i = tid; i < RW * NSEQ; i += THR) {
        const int r = i / NSEQ, t = i - r * NSEQ;
        const int gr = b0 + r;
        const bool ok = r < rows;
        const int gidx = ok ? gr * NSEQ + t : t;
        const int nd = nbr_nid[gidx];
        const int oth = other_ids[ok ? gr : b0];
        float sfv = (nd == oth) ? 1.f : 0.f;
        if (HAS_NODE) sfv += ((int)g_skill[nd] == (int)g_skill[oth]) ? 1.f : 0.f;
        ((int*)s->nid)[i] = nd;
        ((float*)s->sf)[i] = sfv;
        ((float*)s->e0)[i] = edge_raw[(size_t)nbr_eid[gidx] * 4];
        ((float*)s->dt)[i] = ok ? (t_int[gr] - nbr_ts[gidx]) : 0.f;
    }
    for (int i = tid; i < RW * DH; i += THR) ((float*)s->h)[i] = 0.f;
    float hreg = 0.f;                            // gates-role private h element
    __syncthreads();

    const uint32_t teb = smem_u32(s->te);
    const uint32_t hqb = smem_u32(s->h) + (uint32_t)qq * 64;   // quarter offset
    const uint32_t m2b = smem_u32(s->M2s) + (uint32_t)kg * 8;

    for (int c = 0; c < NCH; c++) {
        const int tb_ = c * TC;
        // (1) time encodings for the chunk + Q staging (independent loads, high MLP)
        for (int i = tid; i < TC * RW * TD; i += THR) {
            const int kk = i & 15, p = i >> 4;
            const int rr = p % RW, ii = p / RW;
            s->te[ii][rr][kk] =
                cos_acc(__fadd_rn(__fmul_rn(s->dt[rr][tb_ + ii], s->tw[kk]), s->tb[kk]));
        }
        if (HAS_NODE) {
            // stage Q gathers for all 30 of this thread's slots into gi.
            // Loads are fully independent -> deep MLP hides DRAM/L2 latency.
            int p = sg;
#pragma unroll
            for (int pp = 0; pp < (TC * RW) / 2; pp++) {
                const int r = p % RW, ii = p / RW;
                s->gi[ii][r][kg] = __ldg(&g_Q[(size_t)s->nid[r][tb_ + p / RW] * G3 + kg]);
                p += 2;
            }
        }
        __syncthreads();
        // (2) gi accumulate: gi = [stagedQ] + v0 + sf*v1 + e0*v2 + M@te
        {
            u64 m2r[8];
#pragma unroll
            for (int q = 0; q < 8; q++) m2r[q] = lds_u64(m2b + q * G3 * 8);
            int p = sg;
#pragma unroll 5
            for (int pp = 0; pp < (TC * RW) / 2; pp++) {
                const int r = p % RW, ii = p / RW;
                const uint32_t ta = teb + (uint32_t)(ii * RW + r) * 64;
                u64 A = 0ull, B = 0ull;
#pragma unroll
                for (int q = 0; q < 4; q++) {
                    u64 t0, t1;
                    lds_v2u64(ta + q * 16, t0, t1);
                    A = ffma2(m2r[2 * q], t0, A);
                    B = ffma2(m2r[2 * q + 1], t1, B);
                }
                float lo, hi, lo2, hi2;
                unpack2(A, lo, hi); unpack2(B, lo2, hi2);
                float base =
                    fmaf(s->sf[r][tb_ + ii], v1k, fmaf(s->e0[r][tb_ + ii], v2k, v0k));
                if (HAS_NODE) base += s->gi[ii][r][kg];
                s->gi[ii][r][kg] = base + ((lo + hi) + (lo2 + hi2));
                p += 2;
            }
        }
        __syncthreads();
        // (3) recurrence, TC steps
        for (int ii = 0; ii < TC; ii++) {
            // gh quarter-dots: each thread reads each h quarter-row ONCE for 2 outputs
#pragma unroll
            for (int r = 0; r < RW; r++) {
                const uint32_t ha = hqb + (uint32_t)r * 256;
                u64 h0, h1, h2, h3, h4, h5, h6, h7;
                lds_v2u64(ha,      h0, h1);
                lds_v2u64(ha + 16, h2, h3);
                lds_v2u64(ha + 32, h4, h5);
                lds_v2u64(ha + 48, h6, h7);
                u64 a0 = biA, a1 = 0ull, b0 = biB, b1 = 0ull;
                a0 = ffma2(wA[0], h0, a0); a1 = ffma2(wA[1], h1, a1);
                b0 = ffma2(wB[0], h0, b0); b1 = ffma2(wB[1], h1, b1);
                a0 = ffma2(wA[2], h2, a0); a1 = ffma2(wA[3], h3, a1);
                b0 = ffma2(wB[2], h2, b0); b1 = ffma2(wB[3], h3, b1);
                a0 = ffma2(wA[4], h4, a0); a1 = ffma2(wA[5], h5, a1);
                b0 = ffma2(wB[4], h4, b0); b1 = ffma2(wB[5], h5, b1);
                a0 = ffma2(wA[6], h6, a0); a1 = ffma2(wA[7], h7, a1);
                b0 = ffma2(wB[6], h6, b0); b1 = ffma2(wB[7], h7, b1);
                float lo, hi, lo2, hi2;
                unpack2(a0, lo, hi); unpack2(a1, lo2, hi2);
                const float rA = (lo + hi) + (lo2 + hi2);
                unpack2(b0, lo, hi); unpack2(b1, lo2, hi2);
                const float rB = (lo + hi) + (lo2 + hi2);
                *(float2*)&s->ghQ[r][qq][k0] = make_float2(rA, rB);
            }
            __syncthreads();
            // gates + h update: sum 4 quarter-partials; h kept in register
            {
                const float* gq = s->ghQ[rg][0];
                const float ghr = gq[j]        + gq[G3 + j]        + gq[2*G3 + j]        + gq[3*G3 + j];
                const float ghz = gq[64 + j]   + gq[G3 + 64 + j]   + gq[2*G3 + 64 + j]   + gq[3*G3 + 64 + j];
                const float ghn = gq[128 + j]  + gq[G3 + 128 + j]  + gq[2*G3 + 128 + j]  + gq[3*G3 + 128 + j];
                const float gir = s->gi[ii][rg][j];
                const float giz = s->gi[ii][rg][64 + j];
                const float gin = s->gi[ii][rg][128 + j];
                const float r_ = sigmoid_(gir + ghr);
                const float z_ = sigmoid_(giz + ghz);
                const float n_ = tanh_(fmaf(r_, ghn, gin));
                hreg = fmaf(z_, hreg - n_, n_);
                s->h[rg][j] = hreg;
            }
            __syncthreads();
        }
    }

    // ---- epilogue: emb = h + tail (+ P[epi] for dst); out = emb @ W_out + b_out
    {
        float e = hreg + s->tailv[j];
        if (!HAS_NODE) e += g_P[(size_t)epi_ids[b0 + ((rg < rows) ? rg : 0)] * 64 + j];
        s->gi[0][rg][j] = e;
    }
    __syncthreads();
    if (rg < rows) {
        float acc = b_out[j];
        const float* em = s->gi[0][rg];
#pragma unroll 8
        for (int m = 0; m < 64; m++) acc = fmaf(em[m], W_out[m * 64 + j], acc);
        outp[(size_t)(b0 + rg) * 64 + j] = acc;
    }
}

// ---------------- launch ----------------
extern "C" void kernel_launch(void* const* d_in, const int* in_sizes, int n_in,
                              void* d_out, int out_size) {
    const float* node_raw = (const float*)d_in[0];
    const float* edge_raw = (const float*)d_in[1];
    const int* src_ids = (const int*)d_in[2];
    const int* dst_ids = (const int*)d_in[3];
    const float* t_int = (const float*)d_in[4];
    const int* s_nnid = (const int*)d_in[5];
    const int* s_neid = (const int*)d_in[6];
    const float* s_nts = (const float*)d_in[7];
    const int* d_nnid = (const int*)d_in[8];
    const int* d_neid = (const int*)d_in[9];
    const float* d_nts = (const float*)d_in[10];
    const float* W_feat = (const float*)d_in[11];
    const float* b_feat = (const float*)d_in[12];
    const float* W_edge = (const float*)d_in[13];
    const float* b_edge = (const float*)d_in[14];
    const float* W_time = (const float*)d_in[15];
    const float* b_time = (const float*)d_in[16];
    const float* W_struct = (const float*)d_in[17];
    const float* b_struct = (const float*)d_in[18];
    const float* W_out = (const float*)d_in[19];
    const float* b_out = (const float*)d_in[20];
    const float* time_w = (const float*)d_in[21];
    const float* time_b = (const float*)d_in[22];
    const float* sWih = (const float*)d_in[23];
    const float* sWhh = (const float*)d_in[24];
    const float* sbih = (const float*)d_in[25];
    const float* sbhh = (const float*)d_in[26];
    const float* dWih = (const float*)d_in[27];
    const float* dWhh = (const float*)d_in[28];
    const float* dbih = (const float*)d_in[29];
    const float* dbhh = (const float*)d_in[30];

    float* out = (float*)d_out;

    u64* M2_p; cudaGetSymbolAddress((void**)&M2_p, g_M2);
    float* v_p; cudaGetSymbolAddress((void**)&v_p, g_v);

    const int smem = (int)sizeof(SMF);
    cudaFuncSetAttribute(k_fused<true>, cudaFuncAttributeMaxDynamicSharedMemorySize, smem);
    cudaFuncSetAttribute(k_fused<false>, cudaFuncAttributeMaxDynamicSharedMemorySize, smem);

    k_ww<<<2, 384>>>(W_feat, sWih, dWih, sbih, dbih, W_time, W_struct, W_edge,
                     b_feat, b_edge, b_time, b_struct);
    k_nodeQ<<<NUM_NODES / NB, 256>>>(node_raw);

    const int grid = (BATCH + RW - 1) / RW;
    k_fused<true><<<grid, THR, smem>>>(
        s_nnid, s_neid, s_nts, t_int, dst_ids, dst_ids, edge_raw,
        W_time, time_w, time_b, W_edge, b_feat, b_edge, b_time,
        sWhh, sbhh, M2_p, v_p, W_out, b_out, out);
    k_fused<false><<<grid, THR, smem>>>(
        d_nnid, d_neid, d_nts, t_int, src_ids, dst_ids, edge_raw,
        W_time, time_w, time_b, W_edge, b_feat, b_edge, b_time,
        dWhh, dbhh, M2_p + 8 * G3, v_p + 3 * G3, W_out, b_out,
        out + (size_t)BATCH * DH);
}

// round 15
// speedup vs baseline: 1.6569x; 1.6569x over previous
#include <cuda_runtime.h>
#include <cstddef>
#include <cstdint>

#define BATCH 8192
#define NSEQ 50
#define NUM_NODES 200000
#define TD 16
#define DH 64
#define G3 192
#define RW 6           // batch rows per fused block
#define TC 10          // timesteps per chunk
#define NCH (NSEQ / TC)
#define THR 384
#define NB 32          // nodes per k_nodeQ block

typedef unsigned long long u64;

// ---------------- static device scratch ----------------
__device__ float g_Q[(size_t)NUM_NODES * G3];      // node_raw @ (W_feat @ sWih^T)
__device__ float g_Pd[(size_t)BATCH * DH];         // P[dst_ids[b]] per batch row
__device__ float g_skill[NUM_NODES];
__device__ u64   g_Gp[32 * 256];                   // packed combined [Q|P] weight table
__device__ u64   g_M2[2 * 8 * G3];                 // packed M = W_ih @ W_time^T per side
__device__ float g_v[2 * 3 * G3];                  // v0 (const+bias), v1 (struct), v2 (edge)

// ---------------- packed f32x2 helpers ----------------
__device__ __forceinline__ u64 pack2(float lo, float hi) {
    u64 d; asm("mov.b64 %0, {%1, %2};" : "=l"(d) : "f"(lo), "f"(hi)); return d;
}
__device__ __forceinline__ void unpack2(u64 v, float& lo, float& hi) {
    asm("mov.b64 {%0, %1}, %2;" : "=f"(lo), "=f"(hi) : "l"(v));
}
__device__ __forceinline__ u64 ffma2(u64 a, u64 b, u64 c) {
    u64 d; asm("fma.rn.f32x2 %0, %1, %2, %3;" : "=l"(d) : "l"(a), "l"(b), "l"(c));
    return d;
}
__device__ __forceinline__ void lds_v2u64(uint32_t addr, u64& a, u64& b) {
    asm volatile("ld.shared.v2.b64 {%0, %1}, [%2];" : "=l"(a), "=l"(b) : "r"(addr));
}
__device__ __forceinline__ u64 lds_u64(uint32_t addr) {
    u64 a; asm volatile("ld.shared.b64 %0, [%1];" : "=l"(a) : "r"(addr)); return a;
}
__device__ __forceinline__ uint32_t smem_u32(const void* p) {
    return (uint32_t)__cvta_generic_to_shared(p);
}

// ---------------- math helpers ----------------
__device__ __forceinline__ float cos_acc(float x) {
    const double TP = 6.283185307179586476925287;
    const float C1 = 6.28125f;
    const float C2 = (float)(TP - (double)C1);
    const float C3 = (float)(TP - (double)C1 - (double)((float)(TP - (double)C1)));
    const float INV2PI = 0.15915494309189535f;
    float k = rintf(x * INV2PI);
    float r = fmaf(-k, C1, x);
    r = fmaf(-k, C2, r);
    r = fmaf(-k, C3, r);
    return __cosf(r);
}
__device__ __forceinline__ float sigmoid_(float x) {
    float e = __expf(-x);
    return __fdividef(1.0f, 1.0f + e);
}
__device__ __forceinline__ float tanh_(float x) {
    float e = __expf(-2.0f * x);
    return __fdividef(2.0f, 1.0f + e) - 1.0f;
}

// ---------------- K1: derived weight tables ----------------
__global__ void __launch_bounds__(384) k_ww(
    const float* __restrict__ Wf, const float* __restrict__ sWih,
    const float* __restrict__ dWih, const float* __restrict__ sbih,
    const float* __restrict__ dbih, const float* __restrict__ Wt,
    const float* __restrict__ Wstr, const float* __restrict__ Wedg,
    const float* __restrict__ bf, const float* __restrict__ be,
    const float* __restrict__ bt, const float* __restrict__ bs)
{
    __shared__ float sm[4096];
    const int tid = threadIdx.x;
    if (blockIdx.x == 0) {
        for (int i = tid; i < 4096; i += 384) sm[i] = Wf[i];
        __syncthreads();
        if (tid < 192) {
            const int c = tid;
            float row[64];
            const float4* rp = (const float4*)(sWih + (size_t)c * 64);
#pragma unroll
            for (int q4 = 0; q4 < 16; q4++) {
                float4 v = rp[q4];
                row[4*q4] = v.x; row[4*q4+1] = v.y; row[4*q4+2] = v.z; row[4*q4+3] = v.w;
            }
#pragma unroll
            for (int q = 0; q < 32; q++) {
                float a0 = 0.f, a1 = 0.f;
#pragma unroll
                for (int j = 0; j < 64; j++) {
                    a0 = fmaf(row[j], sm[(2*q)*64 + j], a0);
                    a1 = fmaf(row[j], sm[(2*q+1)*64 + j], a1);
                }
                g_Gp[q * 256 + c] = pack2(a0, a1);
            }
        }
    } else {
        for (int i = tid; i < 1024; i += 384) sm[i] = Wt[i];
        if (tid < 64) {
            sm[1024 + tid] = Wstr[tid];
            sm[1088 + tid] = Wedg[tid];
            sm[1152 + tid] = be[tid] + bt[tid] + 2.f * bs[tid] + bf[tid];  // src C
            sm[1216 + tid] = be[tid] + bt[tid] + bs[tid];                  // dst C
        }
        __syncthreads();
        const int side = tid / G3, k = tid % G3;
        const float* Wih = side ? dWih : sWih;
        const float* bihp = side ? dbih : sbih;
        float row[64];
        const float4* rp = (const float4*)(Wih + (size_t)k * 64);
#pragma unroll
        for (int q4 = 0; q4 < 16; q4++) {
            float4 v = rp[q4];
            row[4*q4] = v.x; row[4*q4+1] = v.y; row[4*q4+2] = v.z; row[4*q4+3] = v.w;
        }
        float M[16];
#pragma unroll
        for (int kk = 0; kk < 16; kk++) {
            float a = 0.f;
#pragma unroll
            for (int j = 0; j < 64; j++) a = fmaf(row[j], sm[kk * 64 + j], a);
            M[kk] = a;
        }
        float v1 = 0.f, v2 = 0.f, v0 = bihp[k];
#pragma unroll
        for (int j = 0; j < 64; j++) {
            v1 = fmaf(row[j], sm[1024 + j], v1);
            v2 = fmaf(row[j], sm[1088 + j], v2);
            v0 = fmaf(row[j], sm[1152 + side * 64 + j], v0);
        }
#pragma unroll
        for (int q = 0; q < 8; q++)
            g_M2[(side * 8 + q) * G3 + k] = pack2(M[2*q], M[2*q+1]);
        g_v[(side * 3 + 0) * G3 + k] = v0;
        g_v[(side * 3 + 1) * G3 + k] = v1;
        g_v[(side * 3 + 2) * G3 + k] = v2;
    }
}

// ---------------- K2: per-node Q (192) + skill tables (Q only) ----------------
__global__ void __launch_bounds__(192) k_nodeQ(const float* __restrict__ nodef) {
    __shared__ __align__(16) float rows[NB][64];
    const int tid = threadIdx.x;
    const int n0 = blockIdx.x * NB;
    for (int i = tid; i < NB * 64; i += 192) ((float*)rows)[i] = nodef[(size_t)n0 * 64 + i];
    __syncthreads();
    u64 w[32];
#pragma unroll
    for (int q = 0; q < 32; q++) w[q] = g_Gp[q * 256 + tid];
    const uint32_t rb = smem_u32(rows);
#pragma unroll 2
    for (int nn = 0; nn < NB; nn++) {
        const uint32_t ra = rb + nn * 256;
        u64 a0 = 0ull, a1 = 0ull;
#pragma unroll
        for (int q = 0; q < 16; q++) {
            u64 p, qq;
            lds_v2u64(ra + q * 16, p, qq);
            a0 = ffma2(w[2*q], p, a0);
            a1 = ffma2(w[2*q+1], qq, a1);
        }
        float lo, hi, lo2, hi2;
        unpack2(a0, lo, hi); unpack2(a1, lo2, hi2);
        g_Q[(size_t)(n0 + nn) * G3 + tid] = (lo + hi) + (lo2 + hi2);
    }
    if (tid < NB) g_skill[n0 + tid] = rows[tid][0];
}

// ---------------- K3: P[dst_ids[b]] for the dst epilogue only ----------------
__global__ void __launch_bounds__(256) k_dstP(const float* __restrict__ nodef,
                                              const float* __restrict__ Wf,
                                              const int* __restrict__ dst_ids) {
    __shared__ float Wsm[4096];
    __shared__ __align__(16) float rowb[4][64];
    const int tid = threadIdx.x;
    for (int i = tid; i < 4096; i += 256) Wsm[i] = Wf[i];
    const int g = tid >> 6, j = tid & 63;
    const int b = blockIdx.x * 4 + g;
    rowb[g][j] = nodef[(size_t)dst_ids[b] * 64 + j];
    __syncthreads();
    float acc = 0.f;
#pragma unroll
    for (int k = 0; k < 64; k++) acc = fmaf(rowb[g][k], Wsm[k * 64 + j], acc);
    g_Pd[(size_t)b * 64 + j] = acc;
}

// ---------------- fused gi + GRU kernel (quarter-split, output-pair gh) ----------------
struct SMF {
    float gi[TC][RW][G3];              // 46080
    float ghQ[RW][4][G3];              // 18432 : gh quarter-partials
    u64   M2s[8][G3];                  // 12288
    __align__(16) float te[TC][RW][TD];//  3840
    __align__(16) float h[RW][DH];     //  1536
    float sf[RW][NSEQ];                //  1200
    float e0[RW][NSEQ];                //  1200
    float dt[RW][NSEQ];                //  1200
    int   nid[RW][NSEQ];               //  1200
    float tailv[DH];                   //   256
    float tw[TD], tb[TD];              //   128
};

template <bool HAS_NODE>
__global__ void __launch_bounds__(THR, 2) k_fused(
    const int* __restrict__ nbr_nid, const int* __restrict__ nbr_eid,
    const float* __restrict__ nbr_ts, const float* __restrict__ t_int,
    const int* __restrict__ other_ids,
    const float* __restrict__ edge_raw, const float* __restrict__ W_time,
    const float* __restrict__ time_w, const float* __restrict__ time_b,
    const float* __restrict__ W_edge, const float* __restrict__ b_feat,
    const float* __restrict__ b_edge, const float* __restrict__ b_time,
    const float* __restrict__ W_hh, const float* __restrict__ b_hh,
    const u64* __restrict__ M2g, const float* __restrict__ vg,
    const float* __restrict__ W_out, const float* __restrict__ b_out,
    float* __restrict__ outp)
{
    extern __shared__ char smraw[];
    SMF* s = (SMF*)smraw;
    const int tid = threadIdx.x;
    const int b0 = blockIdx.x * RW;
    const int rows = min(RW, BATCH - b0);
    // gi role: full 16-dots, slot group
    const int kg = tid % G3, sg = tid / G3;
    // gh role: output pair x quarter
    const int kp = tid % 96, qq = tid / 96;      // kp: outputs 2kp,2kp+1 ; qq: 0..3
    const int k0 = 2 * kp;
    // gates role
    const int rg = tid >> 6, j = tid & 63;

    // persistent regs: W_hh quarter-rows for 2 outputs + packed bias init
    u64 wA[8], wB[8];
    {
        const float4* wpA = (const float4*)(W_hh + (size_t)k0 * 64 + qq * 16);
        const float4* wpB = (const float4*)(W_hh + (size_t)(k0 + 1) * 64 + qq * 16);
#pragma unroll
        for (int q = 0; q < 4; q++) {
            float4 a = wpA[q], b = wpB[q];
            wA[2*q] = pack2(a.x, a.y); wA[2*q+1] = pack2(a.z, a.w);
            wB[2*q] = pack2(b.x, b.y); wB[2*q+1] = pack2(b.z, b.w);
        }
    }
    const u64 biA = qq ? 0ull : pack2(b_hh[k0], 0.f);
    const u64 biB = qq ? 0ull : pack2(b_hh[k0 + 1], 0.f);
    const float v0k = vg[kg], v1k = vg[G3 + kg], v2k = vg[2 * G3 + kg];

    // ---- init ----
    for (int i = tid; i < 8 * G3; i += THR) ((u64*)s->M2s)[i] = M2g[i];
    if (tid < 64) {
        float tl = b_time[tid] + b_edge[tid] + edge_raw[0] * W_edge[tid];
        if (!HAS_NODE) tl += b_feat[tid];
#pragma unroll
        for (int kk = 0; kk < TD; kk++)
            tl = fmaf(cos_acc(time_b[kk]), W_time[kk * 64 + tid], tl);
        s->tailv[tid] = tl;
    } else if (tid < 80) {
        s->tw[tid - 64] = time_w[tid - 64];
        s->tb[tid - 64] = time_b[tid - 64];
    }
    for (int i = tid; i < RW * NSEQ; i += THR) {
        const int r = i / NSEQ, t = i - r * NSEQ;
        const int gr = b0 + r;
        const bool ok = r < rows;
        const int gidx = ok ? gr * NSEQ + t : t;
        const int nd = nbr_nid[gidx];
        const int oth = other_ids[ok ? gr : b0];
        float sfv = (nd == oth) ? 1.f : 0.f;
        if (HAS_NODE) sfv += ((int)g_skill[nd] == (int)g_skill[oth]) ? 1.f : 0.f;
        ((int*)s->nid)[i] = nd;
        ((float*)s->sf)[i] = sfv;
        ((float*)s->e0)[i] = edge_raw[(size_t)nbr_eid[gidx] * 4];
        ((float*)s->dt)[i] = ok ? (t_int[gr] - nbr_ts[gidx]) : 0.f;
    }
    for (int i = tid; i < RW * DH; i += THR) ((float*)s->h)[i] = 0.f;
    float hreg = 0.f;                            // gates-role private h element
    __syncthreads();

    const uint32_t teb = smem_u32(s->te);
    const uint32_t hqb = smem_u32(s->h) + (uint32_t)qq * 64;   // quarter offset
    const uint32_t m2b = smem_u32(s->M2s) + (uint32_t)kg * 8;

    for (int c = 0; c < NCH; c++) {
        const int tb_ = c * TC;
        // (1) time encodings for the chunk
        for (int i = tid; i < TC * RW * TD; i += THR) {
            const int kk = i & 15, p = i >> 4;
            const int rr = p % RW, ii = p / RW;
            s->te[ii][rr][kk] =
                cos_acc(__fadd_rn(__fmul_rn(s->dt[rr][tb_ + ii], s->tw[kk]), s->tb[kk]));
        }
        __syncthreads();
        // (2) gi build: gi = v0 + sf*v1 + e0*v2 + M@te (+ Q gather for src)
        //     Q loads pipelined 3 iterations deep, kept inside the FFMA2 loop.
        {
            u64 m2r[8];
#pragma unroll
            for (int q = 0; q < 8; q++) m2r[q] = lds_u64(m2b + q * G3 * 8);
            const int npairs = (TC * RW) / 2;    // 30
            int p = sg;
            float qb0 = 0.f, qb1 = 0.f, qb2 = 0.f;
            if (HAS_NODE) {
                qb0 = g_Q[(size_t)s->nid[p % RW][tb_ + p / RW] * G3 + kg];
                qb1 = g_Q[(size_t)s->nid[(p + 2) % RW][tb_ + (p + 2) / RW] * G3 + kg];
                qb2 = g_Q[(size_t)s->nid[(p + 4) % RW][tb_ + (p + 4) / RW] * G3 + kg];
            }
#pragma unroll 3
            for (int pp = 0; pp < npairs; pp++) {
                const int r = p % RW, ii = p / RW;
                float qn = 0.f;
                if (HAS_NODE && pp + 3 < npairs) {
                    const int p6 = p + 6;
                    qn = g_Q[(size_t)s->nid[p6 % RW][tb_ + p6 / RW] * G3 + kg];
                }
                const uint32_t ta = teb + (uint32_t)(ii * RW + r) * 64;
                u64 A = 0ull, B = 0ull;
#pragma unroll
                for (int q = 0; q < 4; q++) {
                    u64 t0, t1;
                    lds_v2u64(ta + q * 16, t0, t1);
                    A = ffma2(m2r[2 * q], t0, A);
                    B = ffma2(m2r[2 * q + 1], t1, B);
                }
                float lo, hi, lo2, hi2;
                unpack2(A, lo, hi); unpack2(B, lo2, hi2);
                const float base =
                    fmaf(s->sf[r][tb_ + ii], v1k, fmaf(s->e0[r][tb_ + ii], v2k, v0k));
                s->gi[ii][r][kg] = base + qb0 + ((lo + hi) + (lo2 + hi2));
                qb0 = qb1; qb1 = qb2; qb2 = qn;
                p += 2;
            }
        }
        __syncthreads();
        // (3) recurrence, TC steps
        for (int ii = 0; ii < TC; ii++) {
            // gh quarter-dots: each thread reads each h quarter-row ONCE for 2 outputs
#pragma unroll
            for (int r = 0; r < RW; r++) {
                const uint32_t ha = hqb + (uint32_t)r * 256;
                u64 h0, h1, h2, h3, h4, h5, h6, h7;
                lds_v2u64(ha,      h0, h1);
                lds_v2u64(ha + 16, h2, h3);
                lds_v2u64(ha + 32, h4, h5);
                lds_v2u64(ha + 48, h6, h7);
                u64 a0 = biA, a1 = 0ull, b0 = biB, b1 = 0ull;
                a0 = ffma2(wA[0], h0, a0); a1 = ffma2(wA[1], h1, a1);
                b0 = ffma2(wB[0], h0, b0); b1 = ffma2(wB[1], h1, b1);
                a0 = ffma2(wA[2], h2, a0); a1 = ffma2(wA[3], h3, a1);
                b0 = ffma2(wB[2], h2, b0); b1 = ffma2(wB[3], h3, b1);
                a0 = ffma2(wA[4], h4, a0); a1 = ffma2(wA[5], h5, a1);
                b0 = ffma2(wB[4], h4, b0); b1 = ffma2(wB[5], h5, b1);
                a0 = ffma2(wA[6], h6, a0); a1 = ffma2(wA[7], h7, a1);
                b0 = ffma2(wB[6], h6, b0); b1 = ffma2(wB[7], h7, b1);
                float lo, hi, lo2, hi2;
                unpack2(a0, lo, hi); unpack2(a1, lo2, hi2);
                const float rA = (lo + hi) + (lo2 + hi2);
                unpack2(b0, lo, hi); unpack2(b1, lo2, hi2);
                const float rB = (lo + hi) + (lo2 + hi2);
                *(float2*)&s->ghQ[r][qq][k0] = make_float2(rA, rB);
            }
            __syncthreads();
            // gates + h update: sum 4 quarter-partials; h kept in register
            {
                const float* gq = s->ghQ[rg][0];
                const float ghr = gq[j]        + gq[G3 + j]        + gq[2*G3 + j]        + gq[3*G3 + j];
                const float ghz = gq[64 + j]   + gq[G3 + 64 + j]   + gq[2*G3 + 64 + j]   + gq[3*G3 + 64 + j];
                const float ghn = gq[128 + j]  + gq[G3 + 128 + j]  + gq[2*G3 + 128 + j]  + gq[3*G3 + 128 + j];
                const float gir = s->gi[ii][rg][j];
                const float giz = s->gi[ii][rg][64 + j];
                const float gin = s->gi[ii][rg][128 + j];
                const float r_ = sigmoid_(gir + ghr);
                const float z_ = sigmoid_(giz + ghz);
                const float n_ = tanh_(fmaf(r_, ghn, gin));
                hreg = fmaf(z_, hreg - n_, n_);
                s->h[rg][j] = hreg;
            }
            __syncthreads();
        }
    }

    // ---- epilogue: emb = h + tail (+ Pd for dst); out = emb @ W_out + b_out
    {
        float e = hreg + s->tailv[j];
        if (!HAS_NODE) e += g_Pd[(size_t)(b0 + ((rg < rows) ? rg : 0)) * 64 + j];
        s->gi[0][rg][j] = e;
    }
    __syncthreads();
    if (rg < rows) {
        float acc = b_out[j];
        const float* em = s->gi[0][rg];
#pragma unroll 8
        for (int m = 0; m < 64; m++) acc = fmaf(em[m], W_out[m * 64 + j], acc);
        outp[(size_t)(b0 + rg) * 64 + j] = acc;
    }
}

// ---------------- launch ----------------
extern "C" void kernel_launch(void* const* d_in, const int* in_sizes, int n_in,
                              void* d_out, int out_size) {
    const float* node_raw = (const float*)d_in[0];
    const float* edge_raw = (const float*)d_in[1];
    const int* src_ids = (const int*)d_in[2];
    const int* dst_ids = (const int*)d_in[3];
    const float* t_int = (const float*)d_in[4];
    const int* s_nnid = (const int*)d_in[5];
    const int* s_neid = (const int*)d_in[6];
    const float* s_nts = (const float*)d_in[7];
    const int* d_nnid = (const int*)d_in[8];
    const int* d_neid = (const int*)d_in[9];
    const float* d_nts = (const float*)d_in[10];
    const float* W_feat = (const float*)d_in[11];
    const float* b_feat = (const float*)d_in[12];
    const float* W_edge = (const float*)d_in[13];
    const float* b_edge = (const float*)d_in[14];
    const float* W_time = (const float*)d_in[15];
    const float* b_time = (const float*)d_in[16];
    const float* W_struct = (const float*)d_in[17];
    const float* b_struct = (const float*)d_in[18];
    const float* W_out = (const float*)d_in[19];
    const float* b_out = (const float*)d_in[20];
    const float* time_w = (const float*)d_in[21];
    const float* time_b = (const float*)d_in[22];
    const float* sWih = (const float*)d_in[23];
    const float* sWhh = (const float*)d_in[24];
    const float* sbih = (const float*)d_in[25];
    const float* sbhh = (const float*)d_in[26];
    const float* dWih = (const float*)d_in[27];
    const float* dWhh = (const float*)d_in[28];
    const float* dbih = (const float*)d_in[29];
    const float* dbhh = (const float*)d_in[30];

    float* out = (float*)d_out;

    u64* M2_p; cudaGetSymbolAddress((void**)&M2_p, g_M2);
    float* v_p; cudaGetSymbolAddress((void**)&v_p, g_v);

    const int smem = (int)sizeof(SMF);
    cudaFuncSetAttribute(k_fused<true>, cudaFuncAttributeMaxDynamicSharedMemorySize, smem);
    cudaFuncSetAttribute(k_fused<false>, cudaFuncAttributeMaxDynamicSharedMemorySize, smem);

    k_ww<<<2, 384>>>(W_feat, sWih, dWih, sbih, dbih, W_time, W_struct, W_edge,
                     b_feat, b_edge, b_time, b_struct);
    k_dstP<<<BATCH / 4, 256>>>(node_raw, W_feat, dst_ids);
    k_nodeQ<<<NUM_NODES / NB, 192>>>(node_raw);

    const int grid = (BATCH + RW - 1) / RW;
    k_fused<true><<<grid, THR, smem>>>(
        s_nnid, s_neid, s_nts, t_int, dst_ids, edge_raw,
        W_time, time_w, time_b, W_edge, b_feat, b_edge, b_time,
        sWhh, sbhh, M2_p, v_p, W_out, b_out, out);
    k_fused<false><<<grid, THR, smem>>>(
        d_nnid, d_neid, d_nts, t_int, src_ids, edge_raw,
        W_time, time_w, time_b, W_edge, b_feat, b_edge, b_time,
        dWhh, dbhh, M2_p + 8 * G3, v_p + 3 * G3, W_out, b_out,
        out + (size_t)BATCH * DH);
}

// round 16
// speedup vs baseline: 1.6596x; 1.0016x over previous
#include <cuda_runtime.h>
#include <cstddef>
#include <cstdint>

#define BATCH 8192
#define NSEQ 50
#define NUM_NODES 200000
#define TD 16
#define DH 64
#define G3 192
#define RW 6           // batch rows per fused block
#define TC 10          // timesteps per chunk
#define NCH (NSEQ / TC)
#define THR 384
#define NB 32          // nodes per k_nodeQ block

typedef unsigned long long u64;

// ---------------- static device scratch ----------------
__device__ float g_Q[(size_t)NUM_NODES * G3];      // node_raw @ (W_feat @ sWih^T)
__device__ float g_Pd[(size_t)BATCH * DH];         // P[dst_ids[b]] per batch row
__device__ float g_skill[NUM_NODES];
__device__ u64   g_Gp[32 * 256];                   // packed Q-weight table
__device__ u64   g_M2[2 * 8 * G3];                 // packed M = W_ih @ W_time^T per side
__device__ float g_v[2 * 3 * G3];                  // v0 (const+bias), v1 (struct), v2 (edge)

// ---------------- packed f32x2 helpers ----------------
__device__ __forceinline__ u64 pack2(float lo, float hi) {
    u64 d; asm("mov.b64 %0, {%1, %2};" : "=l"(d) : "f"(lo), "f"(hi)); return d;
}
__device__ __forceinline__ void unpack2(u64 v, float& lo, float& hi) {
    asm("mov.b64 {%0, %1}, %2;" : "=f"(lo), "=f"(hi) : "l"(v));
}
__device__ __forceinline__ u64 ffma2(u64 a, u64 b, u64 c) {
    u64 d; asm("fma.rn.f32x2 %0, %1, %2, %3;" : "=l"(d) : "l"(a), "l"(b), "l"(c));
    return d;
}
__device__ __forceinline__ void lds_v2u64(uint32_t addr, u64& a, u64& b) {
    asm volatile("ld.shared.v2.b64 {%0, %1}, [%2];" : "=l"(a), "=l"(b) : "r"(addr));
}
__device__ __forceinline__ u64 lds_u64(uint32_t addr) {
    u64 a; asm volatile("ld.shared.b64 %0, [%1];" : "=l"(a) : "r"(addr)); return a;
}
__device__ __forceinline__ uint32_t smem_u32(const void* p) {
    return (uint32_t)__cvta_generic_to_shared(p);
}

// ---------------- math helpers ----------------
__device__ __forceinline__ float cos_acc(float x) {
    const double TP = 6.283185307179586476925287;
    const float C1 = 6.28125f;
    const float C2 = (float)(TP - (double)C1);
    const float C3 = (float)(TP - (double)C1 - (double)((float)(TP - (double)C1)));
    const float INV2PI = 0.15915494309189535f;
    float k = rintf(x * INV2PI);
    float r = fmaf(-k, C1, x);
    r = fmaf(-k, C2, r);
    r = fmaf(-k, C3, r);
    return __cosf(r);
}
__device__ __forceinline__ float sigmoid_(float x) {
    float e = __expf(-x);
    return __fdividef(1.0f, 1.0f + e);
}
__device__ __forceinline__ float tanh_(float x) {
    float e = __expf(-2.0f * x);
    return __fdividef(2.0f, 1.0f + e) - 1.0f;
}

// ---------------- K1a: Gp (packed Q-weight) table, 8 blocks ----------------
__global__ void __launch_bounds__(384) k_gp(const float* __restrict__ Wf,
                                            const float* __restrict__ sWih) {
    __shared__ float Wsm[4096];
    __shared__ float rows[24][65];
    const int tid = threadIdx.x;
    for (int i = tid; i < 4096; i += 384) Wsm[i] = Wf[i];
    const int c0 = blockIdx.x * 24;
    for (int i = tid; i < 24 * 64; i += 384)
        rows[i >> 6][i & 63] = sWih[(size_t)c0 * 64 + i];
    __syncthreads();
    const int c = tid % 24, qg = tid / 24;    // qg 0..15
    const float* row = rows[c];
#pragma unroll
    for (int qi = 0; qi < 2; qi++) {
        const int q = qg * 2 + qi;
        float a0 = 0.f, a1 = 0.f;
#pragma unroll 8
        for (int j = 0; j < 64; j++) {
            a0 = fmaf(row[j], Wsm[(2 * q) * 64 + j], a0);
            a1 = fmaf(row[j], Wsm[(2 * q + 1) * 64 + j], a1);
        }
        g_Gp[q * 256 + c0 + c] = pack2(a0, a1);
    }
}

// ---------------- K1b: M2 / v vectors for both sides ----------------
__global__ void __launch_bounds__(384) k_mv(
    const float* __restrict__ sWih, const float* __restrict__ dWih,
    const float* __restrict__ sbih, const float* __restrict__ dbih,
    const float* __restrict__ Wt, const float* __restrict__ Wstr,
    const float* __restrict__ Wedg, const float* __restrict__ bf,
    const float* __restrict__ be, const float* __restrict__ bt,
    const float* __restrict__ bs)
{
    __shared__ float sm[1280];
    const int tid = threadIdx.x;
    for (int i = tid; i < 1024; i += 384) sm[i] = Wt[i];
    if (tid < 64) {
        sm[1024 + tid] = Wstr[tid];
        sm[1088 + tid] = Wedg[tid];
        sm[1152 + tid] = be[tid] + bt[tid] + 2.f * bs[tid] + bf[tid];  // src C
        sm[1216 + tid] = be[tid] + bt[tid] + bs[tid];                  // dst C
    }
    __syncthreads();
    const int side = tid / G3, k = tid % G3;
    const float* Wih = side ? dWih : sWih;
    const float* bihp = side ? dbih : sbih;
    float row[64];
    const float4* rp = (const float4*)(Wih + (size_t)k * 64);
#pragma unroll
    for (int q4 = 0; q4 < 16; q4++) {
        float4 v = rp[q4];
        row[4*q4] = v.x; row[4*q4+1] = v.y; row[4*q4+2] = v.z; row[4*q4+3] = v.w;
    }
    float M[16];
#pragma unroll
    for (int kk = 0; kk < 16; kk++) {
        float a = 0.f;
#pragma unroll
        for (int j = 0; j < 64; j++) a = fmaf(row[j], sm[kk * 64 + j], a);
        M[kk] = a;
    }
    float v1 = 0.f, v2 = 0.f, v0 = bihp[k];
#pragma unroll
    for (int j = 0; j < 64; j++) {
        v1 = fmaf(row[j], sm[1024 + j], v1);
        v2 = fmaf(row[j], sm[1088 + j], v2);
        v0 = fmaf(row[j], sm[1152 + side * 64 + j], v0);
    }
#pragma unroll
    for (int q = 0; q < 8; q++)
        g_M2[(side * 8 + q) * G3 + k] = pack2(M[2*q], M[2*q+1]);
    g_v[(side * 3 + 0) * G3 + k] = v0;
    g_v[(side * 3 + 1) * G3 + k] = v1;
    g_v[(side * 3 + 2) * G3 + k] = v2;
}

// ---------------- K2: per-node Q (192) + skill tables ----------------
__global__ void __launch_bounds__(192) k_nodeQ(const float* __restrict__ nodef) {
    __shared__ __align__(16) float rows[NB][64];
    const int tid = threadIdx.x;
    const int n0 = blockIdx.x * NB;
    for (int i = tid; i < NB * 64; i += 192) ((float*)rows)[i] = nodef[(size_t)n0 * 64 + i];
    __syncthreads();
    u64 w[32];
#pragma unroll
    for (int q = 0; q < 32; q++) w[q] = g_Gp[q * 256 + tid];
    const uint32_t rb = smem_u32(rows);
#pragma unroll 2
    for (int nn = 0; nn < NB; nn++) {
        const uint32_t ra = rb + nn * 256;
        u64 a0 = 0ull, a1 = 0ull;
#pragma unroll
        for (int q = 0; q < 16; q++) {
            u64 p, qq;
            lds_v2u64(ra + q * 16, p, qq);
            a0 = ffma2(w[2*q], p, a0);
            a1 = ffma2(w[2*q+1], qq, a1);
        }
        float lo, hi, lo2, hi2;
        unpack2(a0, lo, hi); unpack2(a1, lo2, hi2);
        g_Q[(size_t)(n0 + nn) * G3 + tid] = (lo + hi) + (lo2 + hi2);
    }
    if (tid < NB) g_skill[n0 + tid] = rows[tid][0];
}

// ---------------- K3: P[dst_ids[b]] for the dst epilogue only ----------------
__global__ void __launch_bounds__(256) k_dstP(const float* __restrict__ nodef,
                                              const float* __restrict__ Wf,
                                              const int* __restrict__ dst_ids) {
    __shared__ float Wsm[4096];
    __shared__ __align__(16) float rowb[4][64];
    const int tid = threadIdx.x;
    for (int i = tid; i < 4096; i += 256) Wsm[i] = Wf[i];
    const int g = tid >> 6, j = tid & 63;
    const int b = blockIdx.x * 4 + g;
    rowb[g][j] = nodef[(size_t)dst_ids[b] * 64 + j];
    __syncthreads();
    float acc = 0.f;
#pragma unroll
    for (int k = 0; k < 64; k++) acc = fmaf(rowb[g][k], Wsm[k * 64 + j], acc);
    g_Pd[(size_t)b * 64 + j] = acc;
}

// ---------------- fused gi + GRU kernel (merged sides, quarter-split gh) --------
struct SMF {
    float gi[TC][RW][G3];              // 46080
    float ghQ[RW][4][G3];              // 18432
    u64   M2s[8][G3];                  // 12288
    __align__(16) float te[TC][RW][TD];//  3840
    __align__(16) float h[RW][DH];     //  1536
    float sf[RW][NSEQ];                //  1200
    float e0[RW][NSEQ];                //  1200
    float dt[RW][NSEQ];                //  1200
    int   nid[RW][NSEQ];               //  1200
    float tailv[DH];                   //   256
    float tw[TD], tb[TD];              //   128
};

__global__ void __launch_bounds__(THR, 2) k_fused(
    const int* __restrict__ s_nnid, const int* __restrict__ s_neid,
    const float* __restrict__ s_nts,
    const int* __restrict__ d_nnid, const int* __restrict__ d_neid,
    const float* __restrict__ d_nts,
    const float* __restrict__ t_int,
    const int* __restrict__ src_ids, const int* __restrict__ dst_ids,
    const float* __restrict__ edge_raw, const float* __restrict__ W_time,
    const float* __restrict__ time_w, const float* __restrict__ time_b,
    const float* __restrict__ W_edge, const float* __restrict__ b_feat,
    const float* __restrict__ b_edge, const float* __restrict__ b_time,
    const float* __restrict__ sWhh, const float* __restrict__ sbhh,
    const float* __restrict__ dWhh, const float* __restrict__ dbhh,
    const float* __restrict__ W_out, const float* __restrict__ b_out,
    float* __restrict__ out)
{
    extern __shared__ char smraw[];
    SMF* s = (SMF*)smraw;
    const int tid = threadIdx.x;
    const int side = blockIdx.x & 1;             // 0 = src (has node), 1 = dst
    const bool has_node = (side == 0);
    const int b0 = (blockIdx.x >> 1) * RW;
    const int rows = min(RW, BATCH - b0);
    const int* nbr_nid = side ? d_nnid : s_nnid;
    const int* nbr_eid = side ? d_neid : s_neid;
    const float* nbr_ts = side ? d_nts : s_nts;
    const int* other_ids = side ? src_ids : dst_ids;
    const float* W_hh = side ? dWhh : sWhh;
    const float* b_hh = side ? dbhh : sbhh;
    const u64* M2g = g_M2 + side * 8 * G3;
    const float* vg = g_v + side * 3 * G3;
    float* outp = out + (size_t)side * BATCH * DH;

    // gi role
    const int kg = tid % G3, sg = tid / G3;
    // gh role: output pair x quarter
    const int kp = tid % 96, qq = tid / 96;
    const int k0 = 2 * kp;
    // gates role
    const int rg = tid >> 6, j = tid & 63;

    u64 wA[8], wB[8];
    {
        const float4* wpA = (const float4*)(W_hh + (size_t)k0 * 64 + qq * 16);
        const float4* wpB = (const float4*)(W_hh + (size_t)(k0 + 1) * 64 + qq * 16);
#pragma unroll
        for (int q = 0; q < 4; q++) {
            float4 a = wpA[q], b = wpB[q];
            wA[2*q] = pack2(a.x, a.y); wA[2*q+1] = pack2(a.z, a.w);
            wB[2*q] = pack2(b.x, b.y); wB[2*q+1] = pack2(b.z, b.w);
        }
    }
    const u64 biA = qq ? 0ull : pack2(b_hh[k0], 0.f);
    const u64 biB = qq ? 0ull : pack2(b_hh[k0 + 1], 0.f);
    const float v0k = vg[kg], v1k = vg[G3 + kg], v2k = vg[2 * G3 + kg];

    // ---- init ----
    for (int i = tid; i < 8 * G3; i += THR) ((u64*)s->M2s)[i] = M2g[i];
    if (tid < 64) {
        float tl = b_time[tid] + b_edge[tid] + edge_raw[0] * W_edge[tid];
        if (!has_node) tl += b_feat[tid];
#pragma unroll
        for (int kk = 0; kk < TD; kk++)
            tl = fmaf(cos_acc(time_b[kk]), W_time[kk * 64 + tid], tl);
        s->tailv[tid] = tl;
    } else if (tid < 80) {
        s->tw[tid - 64] = time_w[tid - 64];
        s->tb[tid - 64] = time_b[tid - 64];
    }
    for (int i = tid; i < RW * NSEQ; i += THR) {
        const int r = i / NSEQ, t = i - r * NSEQ;
        const int gr = b0 + r;
        const bool ok = r < rows;
        const int gidx = ok ? gr * NSEQ + t : t;
        const int nd = nbr_nid[gidx];
        const int oth = other_ids[ok ? gr : b0];
        float sfv = (nd == oth) ? 1.f : 0.f;
        if (has_node) sfv += ((int)g_skill[nd] == (int)g_skill[oth]) ? 1.f : 0.f;
        ((int*)s->nid)[i] = nd;
        ((float*)s->sf)[i] = sfv;
        ((float*)s->e0)[i] = edge_raw[(size_t)nbr_eid[gidx] * 4];
        ((float*)s->dt)[i] = ok ? (t_int[gr] - nbr_ts[gidx]) : 0.f;
    }
    for (int i = tid; i < RW * DH; i += THR) ((float*)s->h)[i] = 0.f;
    float hreg = 0.f;
    __syncthreads();

    const uint32_t teb = smem_u32(s->te);
    const uint32_t hqb = smem_u32(s->h) + (uint32_t)qq * 64;
    const uint32_t m2b = smem_u32(s->M2s) + (uint32_t)kg * 8;

    for (int c = 0; c < NCH; c++) {
        const int tb_ = c * TC;
        // (1) time encodings for the chunk
        for (int i = tid; i < TC * RW * TD; i += THR) {
            const int kk = i & 15, p = i >> 4;
            const int rr = p % RW, ii = p / RW;
            s->te[ii][rr][kk] =
                cos_acc(__fadd_rn(__fmul_rn(s->dt[rr][tb_ + ii], s->tw[kk]), s->tb[kk]));
        }
        __syncthreads();
        // (2) gi build: gi = v0 + sf*v1 + e0*v2 + M@te (+ Q gather for src)
        //     Q loads pipelined 3 deep; incremental (r, ii) indices (p+6 => same r, ii+1)
        {
            u64 m2r[8];
#pragma unroll
            for (int q = 0; q < 8; q++) m2r[q] = lds_u64(m2b + q * G3 * 8);
            int r = sg, ii = 0;
            float qb0 = 0.f, qb1 = 0.f, qb2 = 0.f;
            if (has_node) {
                qb0 = g_Q[(size_t)s->nid[sg][tb_] * G3 + kg];
                qb1 = g_Q[(size_t)s->nid[sg + 2][tb_] * G3 + kg];
                qb2 = g_Q[(size_t)s->nid[sg + 4][tb_] * G3 + kg];
            }
#pragma unroll 3
            for (int pp = 0; pp < (TC * RW) / 2; pp++) {
                float qn = 0.f;
                if (has_node && ii + 1 < TC)
                    qn = g_Q[(size_t)s->nid[r][tb_ + ii + 1] * G3 + kg];
                const uint32_t ta = teb + (uint32_t)(ii * RW + r) * 64;
                u64 A = 0ull, B = 0ull;
#pragma unroll
                for (int q = 0; q < 4; q++) {
                    u64 t0, t1;
                    lds_v2u64(ta + q * 16, t0, t1);
                    A = ffma2(m2r[2 * q], t0, A);
                    B = ffma2(m2r[2 * q + 1], t1, B);
                }
                float lo, hi, lo2, hi2;
                unpack2(A, lo, hi); unpack2(B, lo2, hi2);
                const float base =
                    fmaf(s->sf[r][tb_ + ii], v1k, fmaf(s->e0[r][tb_ + ii], v2k, v0k));
                s->gi[ii][r][kg] = base + qb0 + ((lo + hi) + (lo2 + hi2));
                qb0 = qb1; qb1 = qb2; qb2 = qn;
                r += 2;
                if (r >= RW) { r -= RW; ii++; }
            }
        }
        __syncthreads();
        // (3) recurrence, TC steps
        for (int ii = 0; ii < TC; ii++) {
#pragma unroll
            for (int r = 0; r < RW; r++) {
                const uint32_t ha = hqb + (uint32_t)r * 256;
                u64 h0, h1, h2, h3, h4, h5, h6, h7;
                lds_v2u64(ha,      h0, h1);
                lds_v2u64(ha + 16, h2, h3);
                lds_v2u64(ha + 32, h4, h5);
                lds_v2u64(ha + 48, h6, h7);
                u64 a0 = biA, a1 = 0ull, b0 = biB, b1 = 0ull;
                a0 = ffma2(wA[0], h0, a0); a1 = ffma2(wA[1], h1, a1);
                b0 = ffma2(wB[0], h0, b0); b1 = ffma2(wB[1], h1, b1);
                a0 = ffma2(wA[2], h2, a0); a1 = ffma2(wA[3], h3, a1);
                b0 = ffma2(wB[2], h2, b0); b1 = ffma2(wB[3], h3, b1);
                a0 = ffma2(wA[4], h4, a0); a1 = ffma2(wA[5], h5, a1);
                b0 = ffma2(wB[4], h4, b0); b1 = ffma2(wB[5], h5, b1);
                a0 = ffma2(wA[6], h6, a0); a1 = ffma2(wA[7], h7, a1);
                b0 = ffma2(wB[6], h6, b0); b1 = ffma2(wB[7], h7, b1);
                float lo, hi, lo2, hi2;
                unpack2(a0, lo, hi); unpack2(a1, lo2, hi2);
                const float rA = (lo + hi) + (lo2 + hi2);
                unpack2(b0, lo, hi); unpack2(b1, lo2, hi2);
                const float rB = (lo + hi) + (lo2 + hi2);
                *(float2*)&s->ghQ[r][qq][k0] = make_float2(rA, rB);
            }
            __syncthreads();
            {
                const float* gq = s->ghQ[rg][0];
                const float ghr = gq[j]        + gq[G3 + j]        + gq[2*G3 + j]        + gq[3*G3 + j];
                const float ghz = gq[64 + j]   + gq[G3 + 64 + j]   + gq[2*G3 + 64 + j]   + gq[3*G3 + 64 + j];
                const float ghn = gq[128 + j]  + gq[G3 + 128 + j]  + gq[2*G3 + 128 + j]  + gq[3*G3 + 128 + j];
                const float gir = s->gi[ii][rg][j];
                const float giz = s->gi[ii][rg][64 + j];
                const float gin = s->gi[ii][rg][128 + j];
                const float r_ = sigmoid_(gir + ghr);
                const float z_ = sigmoid_(giz + ghz);
                const float n_ = tanh_(fmaf(r_, ghn, gin));
                hreg = fmaf(z_, hreg - n_, n_);
                s->h[rg][j] = hreg;
            }
            __syncthreads();
        }
    }

    // ---- epilogue ----
    {
        float e = hreg + s->tailv[j];
        if (!has_node) e += g_Pd[(size_t)(b0 + ((rg < rows) ? rg : 0)) * 64 + j];
        s->gi[0][rg][j] = e;
    }
    __syncthreads();
    if (rg < rows) {
        float acc = b_out[j];
        const float* em = s->gi[0][rg];
#pragma unroll 8
        for (int m = 0; m < 64; m++) acc = fmaf(em[m], W_out[m * 64 + j], acc);
        outp[(size_t)(b0 + rg) * 64 + j] = acc;
    }
}

// ---------------- launch ----------------
extern "C" void kernel_launch(void* const* d_in, const int* in_sizes, int n_in,
                              void* d_out, int out_size) {
    const float* node_raw = (const float*)d_in[0];
    const float* edge_raw = (const float*)d_in[1];
    const int* src_ids = (const int*)d_in[2];
    const int* dst_ids = (const int*)d_in[3];
    const float* t_int = (const float*)d_in[4];
    const int* s_nnid = (const int*)d_in[5];
    const int* s_neid = (const int*)d_in[6];
    const float* s_nts = (const float*)d_in[7];
    const int* d_nnid = (const int*)d_in[8];
    const int* d_neid = (const int*)d_in[9];
    const float* d_nts = (const float*)d_in[10];
    const float* W_feat = (const float*)d_in[11];
    const float* b_feat = (const float*)d_in[12];
    const float* W_edge = (const float*)d_in[13];
    const float* b_edge = (const float*)d_in[14];
    const float* W_time = (const float*)d_in[15];
    const float* b_time = (const float*)d_in[16];
    const float* W_struct = (const float*)d_in[17];
    const float* b_struct = (const float*)d_in[18];
    const float* W_out = (const float*)d_in[19];
    const float* b_out = (const float*)d_in[20];
    const float* time_w = (const float*)d_in[21];
    const float* time_b = (const float*)d_in[22];
    const float* sWih = (const float*)d_in[23];
    const float* sWhh = (const float*)d_in[24];
    const float* sbih = (const float*)d_in[25];
    const float* sbhh = (const float*)d_in[26];
    const float* dWih = (const float*)d_in[27];
    const float* dWhh = (const float*)d_in[28];
    const float* dbih = (const float*)d_in[29];
    const float* dbhh = (const float*)d_in[30];

    float* out = (float*)d_out;

    const int smem = (int)sizeof(SMF);
    cudaFuncSetAttribute(k_fused, cudaFuncAttributeMaxDynamicSharedMemorySize, smem);

    k_gp<<<8, 384>>>(W_feat, sWih);
    k_mv<<<1, 384>>>(sWih, dWih, sbih, dbih, W_time, W_struct, W_edge,
                     b_feat, b_edge, b_time, b_struct);
    k_dstP<<<BATCH / 4, 256>>>(node_raw, W_feat, dst_ids);
    k_nodeQ<<<NUM_NODES / NB, 192>>>(node_raw);

    const int grid = 2 * ((BATCH + RW - 1) / RW);
    k_fused<<<grid, THR, smem>>>(
        s_nnid, s_neid, s_nts, d_nnid, d_neid, d_nts, t_int,
        src_ids, dst_ids, edge_raw,
        W_time, time_w, time_b, W_edge, b_feat, b_edge, b_time,
        sWhh, sbhh, dWhh, dbhh, W_out, b_out, out);
}